// round 6
// baseline (speedup 1.0000x reference)
#include <cuda_runtime.h>
#include <math.h>

#define CC 128
#define MID 8
#define SB 32      // blocks per spatial dim
#define SPD 64     // full spatial dim
#define NT 2048    // tiles = 2 * 32 * 32

#define TWO_SQRT2 2.8284271247461903f

// scratch (allocation-free rule: __device__ globals)
__device__ float g_part[2 * CC * 1024];         // [b][c][d*32+h] raw corner sums (1 MB)
__device__ float g_gap[2 * CC];                 // reduced gap
__device__ float g_gmod[2 * CC];                // global-MLP output
__device__ float g_hidp[2 * NT * MID * SB];     // [half][tile][m][w] pre-relu partials (4 MB)

// ---------------------------------------------------------------------------
// Kernel A: corner pass, split by channel-half for 2x parallelism.
// grid = 4096: (tile 0..2047) x (half 0..1). Each CTA:
//   - loads 64 channels x 32 w corners (float4, full-row coalesced)
//   - per-channel gap partials -> g_part
//   - partial hidden (pre-relu, lb1 folded into half 0) -> g_hidp
// ---------------------------------------------------------------------------
__global__ __launch_bounds__(256) void kA(const float* __restrict__ x,
                                          const float* __restrict__ lw1,
                                          const float* __restrict__ lb1) {
    int tile = blockIdx.x >> 1;    // b*1024 + d*32 + h
    int half = blockIdx.x & 1;
    int b = tile >> 10;
    int d = (tile >> 5) & 31;
    int h = tile & 31;
    int t = threadIdx.x;

    __shared__ float s_s[64][SB + 1];   // raw corners, padded
    __shared__ float s_lw1[MID * 64];   // this half's lw1, pre-scaled by 2*sqrt2

    // weights: lw1[m][half*64 + c]
    for (int i = t; i < MID * 64; i += 256) {
        int m = i >> 6, c = i & 63;
        s_lw1[i] = TWO_SQRT2 * lw1[m * CC + half * 64 + c];
    }

    const float* xb = x + ((size_t)b * CC + half * 64) * (SPD * SPD * SPD);
    const size_t row_off = (size_t)(2 * d) * SPD * SPD + (size_t)(2 * h) * SPD;

    {
        int col = t & 15;            // float4 column within the 256B row
        int c0  = t >> 4;            // 0..15
        #pragma unroll
        for (int it = 0; it < 4; it++) {
            int c = it * 16 + c0;    // 0..63
            float4 v = *(const float4*)(xb + (size_t)c * (SPD * SPD * SPD) + row_off + 4 * col);
            s_s[c][2 * col]     = v.x;
            s_s[c][2 * col + 1] = v.z;
        }
    }
    __syncthreads();

    // gap partial: one channel per thread (t < 64), padded smem rows
    if (t < 64) {
        float s = 0.f;
        #pragma unroll 8
        for (int w = 0; w < SB; w++) s += s_s[t][w];
        int ch = half * 64 + t;
        g_part[((size_t)(b * CC + ch) << 10) + (d << 5) + h] = s;
    }

    // partial hidden: 256 (m,w) pairs, dot over this half's 64 channels
    {
        int m = t >> 5;
        int w = t & 31;
        float a = half ? 0.f : lb1[m];
        const float* wrow = &s_lw1[m * 64];
        #pragma unroll 8
        for (int c = 0; c < 64; c++) a = fmaf(wrow[c], s_s[c][w], a);
        g_hidp[(((size_t)half * NT + tile) * MID + m) * SB + w] = a;
    }
}

// ---------------------------------------------------------------------------
// Kernel B: per-(b,c) reduction of 1024 contiguous partials -> gap. 256 CTAs.
// ---------------------------------------------------------------------------
__global__ __launch_bounds__(256) void kRed() {
    int bc = blockIdx.x;
    int t  = threadIdx.x;
    const float4 v = ((const float4*)(g_part + ((size_t)bc << 10)))[t];
    float s = (v.x + v.y) + (v.z + v.w);
    #pragma unroll
    for (int o = 16; o > 0; o >>= 1) s += __shfl_down_sync(0xffffffffu, s, o);
    __shared__ float red[8];
    if ((t & 31) == 0) red[t >> 5] = s;
    __syncthreads();
    if (t == 0) {
        float tot = 0.f;
        #pragma unroll
        for (int i = 0; i < 8; i++) tot += red[i];
        g_gap[bc] = tot * (TWO_SQRT2 / 32768.0f);
    }
}

// ---------------------------------------------------------------------------
// Kernel C: global MLP -> g_gmod. 2 CTAs x 128 threads.
// ---------------------------------------------------------------------------
__global__ __launch_bounds__(128) void kMLP(const float* __restrict__ gw1,
                                            const float* __restrict__ gb1,
                                            const float* __restrict__ gw2,
                                            const float* __restrict__ gb2) {
    int b = blockIdx.x;
    int t = threadIdx.x;
    __shared__ float gap_s[CC];
    __shared__ float hid[MID];
    gap_s[t] = g_gap[b * CC + t];
    __syncthreads();
    if (t < MID) {
        float a = gb1[t];
        #pragma unroll 8
        for (int c = 0; c < CC; c++) a = fmaf(gw1[t * CC + c], gap_s[c], a);
        hid[t] = fmaxf(a, 0.f);
    }
    __syncthreads();
    float a = gb2[t];
    #pragma unroll
    for (int m = 0; m < MID; m++) a = fmaf(gw2[t * MID + m], hid[m], a);
    g_gmod[b * CC + t] = a;
}

// ---------------------------------------------------------------------------
// Kernel D: pure streaming blend; gate built inline from hidden partials:
//   hid[m] = relu(p0[m] + p1[m]);  gate = sigmoid(gmod + lb2 + lw2·hid)
// ---------------------------------------------------------------------------
__global__ __launch_bounds__(256) void kBlend(const float* __restrict__ x,
                                              const float* __restrict__ lw2,
                                              const float* __restrict__ lb2,
                                              float* __restrict__ out) {
    unsigned tid = blockIdx.x * 256u + threadIdx.x;   // 0 .. 4194303
    int w4 = tid & 15;
    int h  = (tid >> 4) & 31;
    int d  = (tid >> 9) & 31;
    int bc = tid >> 14;            // 0..255
    int c  = bc & 127;

    size_t tile = ((size_t)(bc >> 7) << 10) + (d << 5) + h;
    const float* h0 = g_hidp + (tile * MID) * SB + 2 * w4;
    const float* h1 = g_hidp + (((size_t)NT + tile) * MID) * SB + 2 * w4;

    float gl = g_gmod[bc] + __ldg(&lb2[c]);
    float a0 = gl, a1 = gl;
    #pragma unroll
    for (int m = 0; m < MID; m++) {
        float2 p0 = *(const float2*)(h0 + m * SB);
        float2 p1 = *(const float2*)(h1 + m * SB);
        float hx = fmaxf(p0.x + p1.x, 0.f);
        float hy = fmaxf(p0.y + p1.y, 0.f);
        float wm = __ldg(&lw2[c * MID + m]);
        a0 = fmaf(wm, hx, a0);
        a1 = fmaf(wm, hy, a1);
    }
    float g0 = 1.0f / (1.0f + __expf(-a0));
    float g1 = 1.0f / (1.0f + __expf(-a1));

    size_t base = ((size_t)bc * SPD + 2 * d) * (SPD * SPD)
                + (size_t)(2 * h) * SPD + 4 * w4;

    float4 r00 = __ldcs((const float4*)(x + base));
    float4 r01 = __ldcs((const float4*)(x + base + SPD));
    float4 r10 = __ldcs((const float4*)(x + base + SPD * SPD));
    float4 r11 = __ldcs((const float4*)(x + base + SPD * SPD + SPD));

    float m0 = (r00.x + r00.y + r01.x + r01.y + r10.x + r10.y + r11.x + r11.y) * 0.125f;
    float m1 = (r00.z + r00.w + r01.z + r01.w + r10.z + r10.w + r11.z + r11.w) * 0.125f;
    float om0 = (1.0f - g0) * m0;
    float om1 = (1.0f - g1) * m1;

    r00.x = fmaf(g0, r00.x, om0); r00.y = fmaf(g0, r00.y, om0);
    r01.x = fmaf(g0, r01.x, om0); r01.y = fmaf(g0, r01.y, om0);
    r10.x = fmaf(g0, r10.x, om0); r10.y = fmaf(g0, r10.y, om0);
    r11.x = fmaf(g0, r11.x, om0); r11.y = fmaf(g0, r11.y, om0);
    r00.z = fmaf(g1, r00.z, om1); r00.w = fmaf(g1, r00.w, om1);
    r01.z = fmaf(g1, r01.z, om1); r01.w = fmaf(g1, r01.w, om1);
    r10.z = fmaf(g1, r10.z, om1); r10.w = fmaf(g1, r10.w, om1);
    r11.z = fmaf(g1, r11.z, om1); r11.w = fmaf(g1, r11.w, om1);

    __stcs((float4*)(out + base),                   r00);
    __stcs((float4*)(out + base + SPD),             r01);
    __stcs((float4*)(out + base + SPD * SPD),       r10);
    __stcs((float4*)(out + base + SPD * SPD + SPD), r11);
}

// ---------------------------------------------------------------------------
extern "C" void kernel_launch(void* const* d_in, const int* in_sizes, int n_in,
                              void* d_out, int out_size) {
    const float* x   = (const float*)d_in[0];
    const float* gw1 = (const float*)d_in[1];
    const float* gb1 = (const float*)d_in[2];
    const float* gw2 = (const float*)d_in[3];
    const float* gb2 = (const float*)d_in[4];
    const float* lw1 = (const float*)d_in[5];
    const float* lb1 = (const float*)d_in[6];
    const float* lw2 = (const float*)d_in[7];
    const float* lb2 = (const float*)d_in[8];
    float* out = (float*)d_out;

    kA<<<2 * NT, 256>>>(x, lw1, lb1);
    kRed<<<256, 256>>>();
    kMLP<<<2, 128>>>(gw1, gb1, gw2, gb2);
    kBlend<<<16384, 256>>>(x, lw2, lb2, out);
}

// round 7
// speedup vs baseline: 1.0855x; 1.0855x over previous
#include <cuda_runtime.h>
#include <math.h>

#define CC 128
#define MID 8
#define SB 32      // blocks per spatial dim
#define SPD 64     // full spatial dim
#define NT 2048    // tiles = 2 * 32 * 32

#define TWO_SQRT2 2.8284271247461903f

// scratch (allocation-free rule: __device__ globals)
__device__ float g_part[2 * CC * 1024];         // [b][c][d*32+h] raw corner sums (1 MB)
__device__ float g_gap[2 * CC];                 // reduced gap
__device__ float g_gmod[2 * CC];                // global-MLP output
__device__ float g_hid[NT * MID * SB];          // [tile][m][w] hidden acts, post-relu (2 MB)

// ---------------------------------------------------------------------------
// Kernel A (registerized): one CTA per (b,d,h) tile.
//   - 8 float4 corner loads per thread -> registers (no smem round-trip)
//   - gap partials via half-warp shfl butterflies
//   - hidden layer: per-thread partial dots over 8 channels (lw1 = smem
//     broadcast), 16-way cross-warp smem reduce, relu -> g_hid
// Thread map: col = t&15 (float4 column), c0h = t>>4 (channel group 0..15),
// channels covered by a thread: c = it*16 + c0h, it = 0..7.
// ---------------------------------------------------------------------------
__global__ __launch_bounds__(256) void kA(const float* __restrict__ x,
                                          const float* __restrict__ lw1,
                                          const float* __restrict__ lb1) {
    int tile = blockIdx.x;         // b*1024 + d*32 + h
    int b = tile >> 10;
    int d = (tile >> 5) & 31;
    int h = tile & 31;
    int t = threadIdx.x;
    int lane = t & 31;
    int col  = t & 15;             // float4 column -> w = 2col, 2col+1
    int c0h  = t >> 4;             // 0..15 channel group

    __shared__ float s_lw1[MID * CC];       // 4 KB, pre-scaled by 2*sqrt2
    __shared__ float s_hp[16 * MID * SB];   // 16 KB staging: [g][m][w]

    for (int i = t; i < MID * CC; i += 256) s_lw1[i] = TWO_SQRT2 * lw1[i];

    const float* xb = x + (size_t)b * CC * (SPD * SPD * SPD);
    const size_t row_off = (size_t)(2 * d) * SPD * SPD + (size_t)(2 * h) * SPD;

    // corner loads -> registers
    float vx[8], vz[8];
    #pragma unroll
    for (int it = 0; it < 8; it++) {
        int c = it * 16 + c0h;
        float4 v = *(const float4*)(xb + (size_t)c * (SPD * SPD * SPD) + row_off + 4 * col);
        vx[it] = v.x;
        vz[it] = v.z;
    }

    // gap partials: per-channel sum over w via half-warp butterfly
    {
        float gp[8];
        #pragma unroll
        for (int it = 0; it < 8; it++) gp[it] = vx[it] + vz[it];
        #pragma unroll
        for (int o = 1; o < 16; o <<= 1) {
            #pragma unroll
            for (int it = 0; it < 8; it++)
                gp[it] += __shfl_xor_sync(0xffffffffu, gp[it], o);
        }
        if ((lane & 15) == 0) {
            #pragma unroll
            for (int it = 0; it < 8; it++) {
                int c = it * 16 + c0h;
                g_part[((size_t)(b * CC + c) << 10) + (d << 5) + h] = gp[it];
            }
        }
    }

    __syncthreads();   // s_lw1 ready

    // hidden partials: dot over this thread's 8 channels (weights broadcast)
    float a0[MID], a1[MID];
    #pragma unroll
    for (int m = 0; m < MID; m++) { a0[m] = 0.f; a1[m] = 0.f; }
    #pragma unroll
    for (int it = 0; it < 8; it++) {
        int cidx = it * 16 + c0h;
        #pragma unroll
        for (int m = 0; m < MID; m++) {
            float wv = s_lw1[m * CC + cidx];
            a0[m] = fmaf(wv, vx[it], a0[m]);
            a1[m] = fmaf(wv, vz[it], a1[m]);
        }
    }
    // stage: s_hp[g][m][w], g = c0h
    {
        float* hp = s_hp + c0h * (MID * SB);
        #pragma unroll
        for (int m = 0; m < MID; m++) {
            hp[m * SB + 2 * col]     = a0[m];
            hp[m * SB + 2 * col + 1] = a1[m];
        }
    }
    __syncthreads();

    // final reduce: t = m*32 + w; 16 adds + bias + relu
    {
        int m = t >> 5;
        float acc = lb1[m];
        #pragma unroll
        for (int g = 0; g < 16; g++) acc += s_hp[g * (MID * SB) + t];
        g_hid[(size_t)tile * (MID * SB) + t] = fmaxf(acc, 0.f);
    }
}

// ---------------------------------------------------------------------------
// Kernel B: per-(b,c) reduction of 1024 contiguous partials -> gap. 256 CTAs.
// ---------------------------------------------------------------------------
__global__ __launch_bounds__(256) void kRed() {
    int bc = blockIdx.x;
    int t  = threadIdx.x;
    const float4 v = ((const float4*)(g_part + ((size_t)bc << 10)))[t];
    float s = (v.x + v.y) + (v.z + v.w);
    #pragma unroll
    for (int o = 16; o > 0; o >>= 1) s += __shfl_down_sync(0xffffffffu, s, o);
    __shared__ float red[8];
    if ((t & 31) == 0) red[t >> 5] = s;
    __syncthreads();
    if (t == 0) {
        float tot = 0.f;
        #pragma unroll
        for (int i = 0; i < 8; i++) tot += red[i];
        g_gap[bc] = tot * (TWO_SQRT2 / 32768.0f);
    }
}

// ---------------------------------------------------------------------------
// Kernel C: global MLP -> g_gmod. 2 CTAs x 128 threads.
// ---------------------------------------------------------------------------
__global__ __launch_bounds__(128) void kMLP(const float* __restrict__ gw1,
                                            const float* __restrict__ gb1,
                                            const float* __restrict__ gw2,
                                            const float* __restrict__ gb2) {
    int b = blockIdx.x;
    int t = threadIdx.x;
    __shared__ float gap_s[CC];
    __shared__ float hid[MID];
    gap_s[t] = g_gap[b * CC + t];
    __syncthreads();
    if (t < MID) {
        float a = gb1[t];
        #pragma unroll 8
        for (int c = 0; c < CC; c++) a = fmaf(gw1[t * CC + c], gap_s[c], a);
        hid[t] = fmaxf(a, 0.f);
    }
    __syncthreads();
    float a = gb2[t];
    #pragma unroll
    for (int m = 0; m < MID; m++) a = fmaf(gw2[t * MID + m], hid[m], a);
    g_gmod[b * CC + t] = a;
}

// ---------------------------------------------------------------------------
// Kernel D: pure streaming blend with inline gate (R5 shape — proven 77.2us).
// ---------------------------------------------------------------------------
__global__ __launch_bounds__(256) void kBlend(const float* __restrict__ x,
                                              const float* __restrict__ lw2,
                                              const float* __restrict__ lb2,
                                              float* __restrict__ out) {
    unsigned tid = blockIdx.x * 256u + threadIdx.x;   // 0 .. 4194303
    int w4 = tid & 15;
    int h  = (tid >> 4) & 31;
    int d  = (tid >> 9) & 31;
    int bc = tid >> 14;            // 0..255
    int c  = bc & 127;

    size_t tile = ((size_t)(bc >> 7) << 10) + (d << 5) + h;
    const float* hb = g_hid + tile * (MID * SB) + 2 * w4;
    float gl = g_gmod[bc] + __ldg(&lb2[c]);
    float a0 = gl, a1 = gl;
    #pragma unroll
    for (int m = 0; m < MID; m++) {
        float2 hv = *(const float2*)(hb + m * SB);
        float wm = __ldg(&lw2[c * MID + m]);
        a0 = fmaf(wm, hv.x, a0);
        a1 = fmaf(wm, hv.y, a1);
    }
    float g0 = 1.0f / (1.0f + __expf(-a0));
    float g1 = 1.0f / (1.0f + __expf(-a1));

    size_t base = ((size_t)bc * SPD + 2 * d) * (SPD * SPD)
                + (size_t)(2 * h) * SPD + 4 * w4;

    float4 r00 = __ldcs((const float4*)(x + base));
    float4 r01 = __ldcs((const float4*)(x + base + SPD));
    float4 r10 = __ldcs((const float4*)(x + base + SPD * SPD));
    float4 r11 = __ldcs((const float4*)(x + base + SPD * SPD + SPD));

    float m0 = (r00.x + r00.y + r01.x + r01.y + r10.x + r10.y + r11.x + r11.y) * 0.125f;
    float m1 = (r00.z + r00.w + r01.z + r01.w + r10.z + r10.w + r11.z + r11.w) * 0.125f;
    float om0 = (1.0f - g0) * m0;
    float om1 = (1.0f - g1) * m1;

    r00.x = fmaf(g0, r00.x, om0); r00.y = fmaf(g0, r00.y, om0);
    r01.x = fmaf(g0, r01.x, om0); r01.y = fmaf(g0, r01.y, om0);
    r10.x = fmaf(g0, r10.x, om0); r10.y = fmaf(g0, r10.y, om0);
    r11.x = fmaf(g0, r11.x, om0); r11.y = fmaf(g0, r11.y, om0);
    r00.z = fmaf(g1, r00.z, om1); r00.w = fmaf(g1, r00.w, om1);
    r01.z = fmaf(g1, r01.z, om1); r01.w = fmaf(g1, r01.w, om1);
    r10.z = fmaf(g1, r10.z, om1); r10.w = fmaf(g1, r10.w, om1);
    r11.z = fmaf(g1, r11.z, om1); r11.w = fmaf(g1, r11.w, om1);

    __stcs((float4*)(out + base),                   r00);
    __stcs((float4*)(out + base + SPD),             r01);
    __stcs((float4*)(out + base + SPD * SPD),       r10);
    __stcs((float4*)(out + base + SPD * SPD + SPD), r11);
}

// ---------------------------------------------------------------------------
extern "C" void kernel_launch(void* const* d_in, const int* in_sizes, int n_in,
                              void* d_out, int out_size) {
    const float* x   = (const float*)d_in[0];
    const float* gw1 = (const float*)d_in[1];
    const float* gb1 = (const float*)d_in[2];
    const float* gw2 = (const float*)d_in[3];
    const float* gb2 = (const float*)d_in[4];
    const float* lw1 = (const float*)d_in[5];
    const float* lb1 = (const float*)d_in[6];
    const float* lw2 = (const float*)d_in[7];
    const float* lb2 = (const float*)d_in[8];
    float* out = (float*)d_out;

    kA<<<NT, 256>>>(x, lw1, lb1);
    kRed<<<256, 256>>>();
    kMLP<<<2, 128>>>(gw1, gb1, gw2, gb2);
    kBlend<<<16384, 256>>>(x, lw2, lb2, out);
}